// round 16
// baseline (speedup 1.0000x reference)
#include <cuda_runtime.h>
#include <cuda_bf16.h>
#include <cstdint>
#include <cstddef>

#define N_NODES 100000
#define T_SEQ   1024
#define IN_CH   128
#define HID     256
#define G3      768     // 3*HID gate rows

// ---------------- scratch (device globals; no allocations allowed) ----------
#define K1_NCHUNK 37
#define K1_CHUNK  2752  // 43*64; 37*2752 = 101824 >= 100000 (guarded)
#define NSLICES   43    // K-slices of 64 per chunk

__device__ float g_part[K1_NCHUNK * T_SEQ * IN_CH];  // ~19.4 MB partials
__device__ float g_gx[T_SEQ * G3];                   // input gates [1024,768]
__device__ float g_hs[T_SEQ * HID];                  // hidden states [1024,256]

// ============================================================================
// K1 (tensor, legacy mma.sync; cp.async staged, swizzled SMEM transpose) —
// unchanged from rounds 9-15 (proven, HMMA-rate bound).
// ============================================================================
#define WSTR 36                       // words per tile row
#define STG_ROW 128                   // words per staging row (512B)
#define STG_MAT (64 * STG_ROW)        // words per staging matrix (8192)
#define TILE_BASE (4 * STG_MAT)       // staging: [buf][H/X]
#define OFF_AH (TILE_BASE + 0)
#define OFF_AL (TILE_BASE + 128 * WSTR)
#define OFF_BH (TILE_BASE + 256 * WSTR)
#define OFF_BL (TILE_BASE + 384 * WSTR)
#define K1_SMEM_BYTES ((TILE_BASE + 512 * WSTR) * 4)   // 204800 B

__device__ __forceinline__ void mma_bf16(float& c0, float& c1, float& c2, float& c3,
                                         uint32_t a0, uint32_t a1, uint32_t a2,
                                         uint32_t a3, uint32_t b0, uint32_t b1) {
    asm volatile(
        "mma.sync.aligned.m16n8k16.row.col.f32.bf16.bf16.f32 "
        "{%0,%1,%2,%3}, {%4,%5,%6,%7}, {%8,%9}, {%0,%1,%2,%3};"
        : "+f"(c0), "+f"(c1), "+f"(c2), "+f"(c3)
        : "r"(a0), "r"(a1), "r"(a2), "r"(a3), "r"(b0), "r"(b1));
}

__device__ __forceinline__ void k1_issue_slice(const float* __restrict__ H,
                                               const float* __restrict__ X,
                                               int n0s, int t0, int buf,
                                               uint32_t smb, int tid) {
    const uint32_t stH = smb + (uint32_t)((buf * 2 + 0) * STG_MAT) * 4u;
    const uint32_t stX = smb + (uint32_t)((buf * 2 + 1) * STG_MAT) * 4u;
#pragma unroll
    for (int i = 0; i < 4; i++) {
        int ch = tid + i * 512;          // 0..2047
        int r = ch >> 5;                 // staging row 0..63
        int j = ch & 31;                 // 16B chunk within row
        int js = j ^ ((r >> 1) & 7);     // swizzle (low 3 bits)
        uint32_t doff = (uint32_t)(r * 512 + js * 16);
        int n = n0s + r;
        if (n < N_NODES) {
            const float* gH = H + (size_t)n * T_SEQ + t0 + j * 4;
            const float* gX = X + (size_t)n * IN_CH + j * 4;
            asm volatile("cp.async.ca.shared.global [%0], [%1], 16;"
                         :: "r"(stH + doff), "l"(gH));
            asm volatile("cp.async.ca.shared.global [%0], [%1], 16;"
                         :: "r"(stX + doff), "l"(gX));
        } else {
            asm volatile("st.shared.v4.u32 [%0], {%1,%1,%1,%1};"
                         :: "r"(stH + doff), "r"(0u) : "memory");
            asm volatile("st.shared.v4.u32 [%0], {%1,%1,%1,%1};"
                         :: "r"(stX + doff), "r"(0u) : "memory");
        }
    }
}

__global__ void __launch_bounds__(512, 1) k1h_kernel(const float* __restrict__ H,
                                                     const float* __restrict__ X) {
    extern __shared__ uint32_t smw[];
    float* stf = (float*)smw;
    uint32_t smb;
    asm("{ .reg .u64 t; cvta.to.shared.u64 t, %1; cvt.u32.u64 %0, t; }"
        : "=r"(smb) : "l"((const void*)smw));

    const int tid = threadIdx.x;
    const int t0 = blockIdx.x * 128;
    const int n0 = blockIdx.y * K1_CHUNK;

    const int kp = tid & 31;
    const int mg = tid >> 5;
    const int kx = kp & 7;

    const int wid = tid >> 5, lane = tid & 31;
    const int wm = wid >> 2, wn = wid & 3;
    const int lr = lane >> 2, lc = lane & 3;

    float c[2][4][4];
#pragma unroll
    for (int mt = 0; mt < 2; mt++)
#pragma unroll
        for (int nt = 0; nt < 4; nt++)
#pragma unroll
            for (int r = 0; r < 4; r++) c[mt][nt][r] = 0.f;

    k1_issue_slice(H, X, n0, t0, 0, smb, tid);
    asm volatile("cp.async.commit_group;" ::: "memory");

    for (int s = 0; s < NSLICES; s++) {
        const int buf = s & 1;

        if (s + 1 < NSLICES) {
            k1_issue_slice(H, X, n0 + (s + 1) * 64, t0, buf ^ 1, smb, tid);
            asm volatile("cp.async.commit_group;" ::: "memory");
            asm volatile("cp.async.wait_group 1;" ::: "memory");
        } else {
            asm volatile("cp.async.wait_group 0;" ::: "memory");
        }
        __syncthreads();   // staging[buf] visible to all

#pragma unroll
        for (int tsel = 0; tsel < 2; tsel++) {
            const int so = (buf * 2 + tsel) * STG_MAT;
            const int offh = tsel ? OFF_BH : OFF_AH;
            const int offl = tsel ? OFF_BL : OFF_AL;
            const float* r0p = stf + so + (2 * kp) * STG_ROW;
            const float* r1p = stf + so + (2 * kp + 1) * STG_ROW;
            float4 v00 = *(const float4*)(r0p + (((2 * mg)     ^ kx) << 2));
            float4 v01 = *(const float4*)(r0p + (((2 * mg + 1) ^ kx) << 2));
            float4 v10 = *(const float4*)(r1p + (((2 * mg)     ^ kx) << 2));
            float4 v11 = *(const float4*)(r1p + (((2 * mg + 1) ^ kx) << 2));
            const float* e0 = &v00.x;
            const float* f0 = &v01.x;
            const float* e1 = &v10.x;
            const float* f1 = &v11.x;
#pragma unroll
            for (int j = 0; j < 8; j++) {
                float v0 = (j < 4) ? e0[j] : f0[j - 4];
                float v1 = (j < 4) ? e1[j] : f1[j - 4];
                __nv_bfloat162 hi2 = __floats2bfloat162_rn(v0, v1);
                float l0 = v0 - __bfloat162float(hi2.x);
                float l1 = v1 - __bfloat162float(hi2.y);
                __nv_bfloat162 lo2 = __floats2bfloat162_rn(l0, l1);
                int m = mg * 8 + j;
                smw[offh + m * WSTR + kp] = *(uint32_t*)&hi2;
                smw[offl + m * WSTR + kp] = *(uint32_t*)&lo2;
            }
        }

        __syncthreads();   // tiles visible

#pragma unroll
        for (int ks = 0; ks < 4; ks++) {
            const int ksw = ks * 8;
            uint32_t ah[2][4], al[2][4], bh[4][2], bl[4][2];
#pragma unroll
            for (int mt = 0; mt < 2; mt++) {
                int row = wm * 32 + mt * 16 + lr;
                const uint32_t* pa = smw + row * WSTR + ksw + lc;
                ah[mt][0] = pa[OFF_AH];
                ah[mt][1] = pa[OFF_AH + 8 * WSTR];
                ah[mt][2] = pa[OFF_AH + 4];
                ah[mt][3] = pa[OFF_AH + 8 * WSTR + 4];
                al[mt][0] = pa[OFF_AL];
                al[mt][1] = pa[OFF_AL + 8 * WSTR];
                al[mt][2] = pa[OFF_AL + 4];
                al[mt][3] = pa[OFF_AL + 8 * WSTR + 4];
            }
#pragma unroll
            for (int nt = 0; nt < 4; nt++) {
                int nrow = wn * 32 + nt * 8 + lr;
                const uint32_t* pb = smw + nrow * WSTR + ksw + lc;
                bh[nt][0] = pb[OFF_BH];
                bh[nt][1] = pb[OFF_BH + 4];
                bl[nt][0] = pb[OFF_BL];
                bl[nt][1] = pb[OFF_BL + 4];
            }
#pragma unroll
            for (int mt = 0; mt < 2; mt++)
#pragma unroll
                for (int nt = 0; nt < 4; nt++) {
                    float* cc = c[mt][nt];
                    mma_bf16(cc[0], cc[1], cc[2], cc[3],
                             ah[mt][0], ah[mt][1], ah[mt][2], ah[mt][3],
                             bh[nt][0], bh[nt][1]);
                    mma_bf16(cc[0], cc[1], cc[2], cc[3],
                             ah[mt][0], ah[mt][1], ah[mt][2], ah[mt][3],
                             bl[nt][0], bl[nt][1]);
                    mma_bf16(cc[0], cc[1], cc[2], cc[3],
                             al[mt][0], al[mt][1], al[mt][2], al[mt][3],
                             bh[nt][0], bh[nt][1]);
                }
        }

        __syncthreads();   // MMA reads done before next slice's stores
    }

    float* pp = g_part + (size_t)blockIdx.y * (T_SEQ * IN_CH);
#pragma unroll
    for (int mt = 0; mt < 2; mt++) {
#pragma unroll
        for (int nt = 0; nt < 4; nt++) {
            int row0 = wm * 32 + mt * 16 + lr;
            int col = wn * 32 + nt * 8 + lc * 2;
            *(float2*)(pp + (size_t)(t0 + row0) * IN_CH + col) =
                make_float2(c[mt][nt][0], c[mt][nt][1]);
            *(float2*)(pp + (size_t)(t0 + row0 + 8) * IN_CH + col) =
                make_float2(c[mt][nt][2], c[mt][nt][3]);
        }
    }
}

// ============================================================================
// K2 (retiled): 128 blocks x 8 t-rows. Each block reduces its 8 ve rows from
// the 37 chunk partials (deterministic per-thread serial sum), then streams
// w_ih ONCE per block (50MB total L2 traffic vs 402MB at 1 block/t):
// per gate-row: 1 LDG.128 of w, 8 in-register dots vs SMEM ve, one 8-value
// butterfly; lanes 0-7 store the 8 t-results.
// ============================================================================
#define GX_TPB 8
__global__ void __launch_bounds__(256) gx_kernel(const float* __restrict__ w_ih,
                                                 const float* __restrict__ b_ih) {
    __shared__ __align__(16) float s_ve[GX_TPB][128];
    const int t0 = blockIdx.x * GX_TPB;
    const int tid = threadIdx.x;

    // partial reduction: 8*128 entries, 4 per thread, serial over 37 chunks
#pragma unroll
    for (int e = 0; e < 4; e++) {
        int idx = tid + e * 256;
        int tt = idx >> 7, col = idx & 127;
        const float* p = g_part + (size_t)(t0 + tt) * IN_CH + col;
        float s = 0.f;
#pragma unroll 4
        for (int c = 0; c < K1_NCHUNK; c++)
            s += p[(size_t)c * (T_SEQ * IN_CH)];
        s_ve[tt][col] = s;
    }
    __syncthreads();

    const int w = tid >> 5, l = tid & 31;
    // preload ve fragments (8 x float4) into registers
    float4 vv[GX_TPB];
#pragma unroll
    for (int tt = 0; tt < GX_TPB; tt++) vv[tt] = *(const float4*)&s_ve[tt][l * 4];

    for (int rr = 0; rr < 96; rr++) {
        int r = w * 96 + rr;
        float4 wv = *(const float4*)(w_ih + (size_t)r * IN_CH + l * 4);
        float p[GX_TPB];
#pragma unroll
        for (int tt = 0; tt < GX_TPB; tt++)
            p[tt] = (wv.x * vv[tt].x + wv.y * vv[tt].y) +
                    (wv.z * vv[tt].z + wv.w * vv[tt].w);
#pragma unroll
        for (int o = 16; o; o >>= 1)
#pragma unroll
            for (int tt = 0; tt < GX_TPB; tt++)
                p[tt] += __shfl_xor_sync(0xffffffffu, p[tt], o);
        if (l < GX_TPB)
            g_gx[(size_t)(t0 + l) * G3 + r] = p[l] + b_ih[r];
    }
}

// ============================================================================
// K3: sequential GRU, 16-CTA cluster x 128 threads — ROUND-12 VERSION
// (proven 603us fabric-latency floor). hnew staged to SMEM (16 floats), one
// __syncthreads (read-certificate + stage-complete), then 64 vector sends:
// thread tid<64 sends 16B (st.async.v4) chunk tid&3 to peer tid>>2.
// ============================================================================
#define GRU_NCTA 16
__device__ __forceinline__ void cluster_sync_() {
    asm volatile("barrier.cluster.arrive.aligned;" ::: "memory");
    asm volatile("barrier.cluster.wait.aligned;" ::: "memory");
}
__device__ __forceinline__ void st_async_v4(uint32_t laddr, uint32_t lbar,
                                            uint32_t peer, float4 v) {
    uint32_t ra, rb;
    asm volatile("mapa.shared::cluster.u32 %0, %1, %2;"
                 : "=r"(ra) : "r"(laddr), "r"(peer));
    asm volatile("mapa.shared::cluster.u32 %0, %1, %2;"
                 : "=r"(rb) : "r"(lbar), "r"(peer));
    asm volatile(
        "st.async.shared::cluster.mbarrier::complete_tx::bytes.v4.b32 "
        "[%0], {%1,%2,%3,%4}, [%5];"
        :: "r"(ra), "r"(__float_as_uint(v.x)), "r"(__float_as_uint(v.y)),
           "r"(__float_as_uint(v.z)), "r"(__float_as_uint(v.w)), "r"(rb)
        : "memory");
}
__device__ __forceinline__ void arm_expect_tx(uint32_t bar, uint32_t bytes) {
    asm volatile("mbarrier.arrive.expect_tx.shared.b64 _, [%0], %1;"
                 :: "r"(bar), "r"(bytes) : "memory");
}
__device__ __forceinline__ void wait_parity_cl(uint32_t bar, uint32_t par) {
    uint32_t done;
    do {
        asm volatile(
            "{\n\t.reg .pred p;\n\t"
            "mbarrier.try_wait.parity.acquire.cluster.shared::cta.b64 p, [%1], %2, 0x989680;\n\t"
            "selp.b32 %0, 1, 0, p;\n\t}"
            : "=r"(done) : "r"(bar), "r"(par) : "memory");
    } while (!done);
}
__device__ __forceinline__ float tanh_ap(float x) {
    float y;
    asm("tanh.approx.f32 %0, %1;" : "=f"(y) : "f"(x));
    return y;
}
__device__ __forceinline__ float sigmoid_ap(float x) {
    return fmaf(0.5f, tanh_ap(0.5f * x), 0.5f);
}

__global__ void __launch_bounds__(128, 1)
gru_kernel(const float* __restrict__ w_hh, const float* __restrict__ b_hh) {
    __shared__ __align__(16) float sh_h[2][256];            // double-buffered h
    __shared__ __align__(16) float sh_stage[16];            // this CTA's hnew
    __shared__ __align__(8) unsigned long long sh_bar[2];   // full barrier per buf

    const int tid = threadIdx.x;
    const int rank = blockIdx.x;       // 0..15
    const int j = tid >> 3;            // slot 0..15
    const int o = tid & 7;             // k-octant 0..7
    const int slot = rank * 16 + j;    // global h index owned by this group

    unsigned long long wr[16], wz[16], wn[16];
#pragma unroll
    for (int i = 0; i < 16; i++) {
        int k = o * 32 + ((i + 2 * o) & 15) * 2;
        wr[i] = *(const unsigned long long*)(w_hh + (size_t)(slot)*256 + k);
        wz[i] = *(const unsigned long long*)(w_hh + (size_t)(256 + slot) * 256 + k);
        wn[i] = *(const unsigned long long*)(w_hh + (size_t)(512 + slot) * 256 + k);
    }
    const float bhr = b_hh[slot];
    const float bhz = b_hh[256 + slot];
    const float bhn = b_hh[512 + slot];

    sh_h[0][tid] = 0.f;   sh_h[0][tid + 128] = 0.f;
    sh_h[1][tid] = 0.f;   sh_h[1][tid + 128] = 0.f;
    uint32_t bbase = (uint32_t)__cvta_generic_to_shared(&sh_bar[0]);
    if (tid == 0) {
        asm volatile("mbarrier.init.shared.b64 [%0], %1;" :: "r"(bbase),     "r"(1) : "memory");
        asm volatile("mbarrier.init.shared.b64 [%0], %1;" :: "r"(bbase + 8), "r"(1) : "memory");
        arm_expect_tx(bbase, 1024u);       // buffer-0 stores (written at step 1)
        arm_expect_tx(bbase + 8, 1024u);   // buffer-1 stores (written at step 0)
    }
    __syncthreads();
    cluster_sync_();   // barriers + h0 visible cluster-wide

    for (int t = 0; t < T_SEQ; t++) {
        const int cur = t & 1, nxt = cur ^ 1;

        // gx loads (h-independent) issued before the wait to hide latency
        const float gxr = g_gx[t * G3 + slot];
        const float gxz = g_gx[t * G3 + 256 + slot];
        const float gxn = g_gx[t * G3 + 512 + slot];

        if (t > 0) {
            wait_parity_cl(bbase + 8u * (uint32_t)cur, ((t - 1) >> 1) & 1);
            if (tid == 0) arm_expect_tx(bbase + 8u * (uint32_t)cur, 1024u);
        }

        const float hprev = sh_h[cur][slot];

        unsigned long long ar = 0ull, az = 0ull, an = 0ull;
        {
            const float* hb = &sh_h[cur][0];
#pragma unroll
            for (int i = 0; i < 16; i++) {
                int k = o * 32 + ((i + 2 * o) & 15) * 2;
                unsigned long long hv = *(const unsigned long long*)(hb + k);
                asm("fma.rn.f32x2 %0, %1, %2, %0;" : "+l"(ar) : "l"(wr[i]), "l"(hv));
                asm("fma.rn.f32x2 %0, %1, %2, %0;" : "+l"(az) : "l"(wz[i]), "l"(hv));
                asm("fma.rn.f32x2 %0, %1, %2, %0;" : "+l"(an) : "l"(wn[i]), "l"(hv));
            }
        }
        float pr, pz, pn;
        {
            float lo, hi;
            asm("mov.b64 {%0, %1}, %2;" : "=f"(lo), "=f"(hi) : "l"(ar)); pr = lo + hi;
            asm("mov.b64 {%0, %1}, %2;" : "=f"(lo), "=f"(hi) : "l"(az)); pz = lo + hi;
            asm("mov.b64 {%0, %1}, %2;" : "=f"(lo), "=f"(hi) : "l"(an)); pn = lo + hi;
        }
#pragma unroll
        for (int d = 1; d < 8; d <<= 1) {
            pr += __shfl_xor_sync(0xffffffffu, pr, d);
            pz += __shfl_xor_sync(0xffffffffu, pz, d);
            pn += __shfl_xor_sync(0xffffffffu, pn, d);
        }

        const float r = sigmoid_ap(gxr + pr + bhr);
        const float z = sigmoid_ap(gxz + pz + bhz);
        const float n = tanh_ap(gxn + r * (pn + bhn));
        const float hnew = n + z * (hprev - n);

        if (o == 0) {
            sh_stage[j] = hnew;
            g_hs[t * HID + slot] = hnew;
        }

        if (t < T_SEQ - 1) {
            // certifies: all reads of sh_h[cur] retired AND sh_stage complete
            __syncthreads();
            if (tid < 64) {
                const int peer = tid >> 2;       // 0..15 (incl. self)
                const int chunk = tid & 3;       // 0..3 (4 slots each)
                float4 v = *(const float4*)&sh_stage[chunk * 4];
                uint32_t laddr = (uint32_t)__cvta_generic_to_shared(
                    &sh_h[nxt][rank * 16 + chunk * 4]);
                st_async_v4(laddr, bbase + 8u * (uint32_t)nxt, (uint32_t)peer, v);
            }
        }
    }
    cluster_sync_();   // drain in-flight traffic before exit
}

// ============================================================================
// K4: logits = hs @ w_attn; alpha = softmax(logits); out = alpha @ hs
// (logits loads vectorized to LDG.128; weighted sum unrolled x4 for MLP)
// ============================================================================
__global__ void __launch_bounds__(1024) attn_kernel(const float* __restrict__ w_attn,
                                                    float* __restrict__ out) {
    __shared__ float s_alpha[1024];
    __shared__ float s_red[1024];
    __shared__ __align__(16) float s_wa[256];
    const int tid = threadIdx.x;
    if (tid < 256) s_wa[tid] = w_attn[tid];
    __syncthreads();

    const int w = tid >> 5, l = tid & 31;
    {
        float4 wa0 = *(const float4*)&s_wa[l * 4];
        float4 wa1 = *(const float4*)&s_wa[128 + l * 4];
        for (int tt = 0; tt < 32; tt++) {
            int t = w * 32 + tt;
            const float4* hr4 = (const float4*)(g_hs + t * HID);
            float4 a = hr4[l];
            float4 b = hr4[32 + l];
            float p = (a.x * wa0.x + a.y * wa0.y) + (a.z * wa0.z + a.w * wa0.w) +
                      (b.x * wa1.x + b.y * wa1.y) + (b.z * wa1.z + b.w * wa1.w);
#pragma unroll
            for (int o = 16; o; o >>= 1) p += __shfl_xor_sync(0xffffffffu, p, o);
            if (l == 0) s_alpha[t] = p;
        }
    }
    __syncthreads();

    float v = s_alpha[tid];
    s_red[tid] = v;
    __syncthreads();
    for (int s = 512; s; s >>= 1) {
        if (tid < s) s_red[tid] = fmaxf(s_red[tid], s_red[tid + s]);
        __syncthreads();
    }
    float m = s_red[0];
    __syncthreads();
    float e = __expf(v - m);
    s_red[tid] = e;
    __syncthreads();
    for (int s = 512; s; s >>= 1) {
        if (tid < s) s_red[tid] = s_red[tid] + s_red[tid + s];
        __syncthreads();
    }
    float inv = 1.f / s_red[0];
    __syncthreads();
    s_alpha[tid] = e * inv;
    __syncthreads();

    const int j = tid & 255, seg = tid >> 8;
    float p0 = 0.f, p1 = 0.f, p2 = 0.f, p3 = 0.f;
    const float* hp = g_hs + (size_t)seg * 256 * HID + j;
    const float* ap = s_alpha + seg * 256;
#pragma unroll 4
    for (int t = 0; t < 256; t += 4) {
        p0 = fmaf(ap[t],     hp[(t)     * HID], p0);
        p1 = fmaf(ap[t + 1], hp[(t + 1) * HID], p1);
        p2 = fmaf(ap[t + 2], hp[(t + 2) * HID], p2);
        p3 = fmaf(ap[t + 3], hp[(t + 3) * HID], p3);
    }
    s_red[tid] = (p0 + p1) + (p2 + p3);
    __syncthreads();
    if (tid < 256)
        out[j] = (s_red[j] + s_red[256 + j]) + (s_red[512 + j] + s_red[768 + j]);
}

// ============================================================================
extern "C" void kernel_launch(void* const* d_in, const int* in_sizes, int n_in,
                              void* d_out, int out_size) {
    const float* X = nullptr;
    const float* H = nullptr;
    const float* w_ih = nullptr;
    const float* w_hh = nullptr;
    const float* b_ih = nullptr;
    const float* b_hh = nullptr;
    const float* w_attn = nullptr;
    for (int i = 0; i < n_in; i++) {
        int s = in_sizes[i];
        const float* p = (const float*)d_in[i];
        if (s == N_NODES * IN_CH)      X = p;
        else if (s == N_NODES * T_SEQ) H = p;
        else if (s == G3 * IN_CH)      w_ih = p;
        else if (s == G3 * HID)        w_hh = p;
        else if (s == G3) { if (!b_ih) b_ih = p; else b_hh = p; }
        else if (s == HID)             w_attn = p;
    }
    float* out = (float*)d_out;

    cudaFuncSetAttribute(k1h_kernel, cudaFuncAttributeMaxDynamicSharedMemorySize,
                         K1_SMEM_BYTES);

    k1h_kernel<<<dim3(8, K1_NCHUNK), 512, K1_SMEM_BYTES>>>(H, X);
    gx_kernel<<<T_SEQ / GX_TPB, 256>>>(w_ih, b_ih);

    // GRU: 16-CTA cluster (non-portable size), runtime cluster attribute
    cudaFuncSetAttribute(gru_kernel,
                         cudaFuncAttributeNonPortableClusterSizeAllowed, 1);
    {
        cudaLaunchConfig_t cfg = {};
        cfg.gridDim = dim3(GRU_NCTA, 1, 1);
        cfg.blockDim = dim3(128, 1, 1);
        cfg.dynamicSmemBytes = 0;
        cudaLaunchAttribute attrs[1];
        attrs[0].id = cudaLaunchAttributeClusterDimension;
        attrs[0].val.clusterDim = {GRU_NCTA, 1, 1};
        cfg.attrs = attrs;
        cfg.numAttrs = 1;
        cudaLaunchKernelEx(&cfg, gru_kernel, w_hh, b_hh);
    }

    attn_kernel<<<1, 1024>>>(w_attn, out);
}

// round 17
// speedup vs baseline: 1.5401x; 1.5401x over previous
#include <cuda_runtime.h>
#include <cuda_bf16.h>
#include <cstdint>
#include <cstddef>

#define N_NODES 100000
#define T_SEQ   1024
#define IN_CH   128
#define HID     256
#define G3      768     // 3*HID gate rows

// ---------------- scratch (device globals; no allocations allowed) ----------
#define K1_NCHUNK 37
#define K1_CHUNK  2752  // 43*64; 37*2752 = 101824 >= 100000 (guarded)
#define NSLICES   43    // K-slices of 64 per chunk

__device__ float g_part[K1_NCHUNK * T_SEQ * IN_CH];  // ~19.4 MB partials
__device__ float g_ve[T_SEQ * IN_CH];                // visit_emb [1024,128]
__device__ float g_gx[T_SEQ * G3];                   // input gates [1024,768]
__device__ float g_hs[T_SEQ * HID];                  // hidden states [1024,256]

// ============================================================================
// K1 (tensor, legacy mma.sync; cp.async staged, swizzled SMEM transpose) —
// round-12-proven (HMMA-rate bound, ~140us).
// ============================================================================
#define WSTR 36                       // words per tile row
#define STG_ROW 128                   // words per staging row (512B)
#define STG_MAT (64 * STG_ROW)        // words per staging matrix (8192)
#define TILE_BASE (4 * STG_MAT)       // staging: [buf][H/X]
#define OFF_AH (TILE_BASE + 0)
#define OFF_AL (TILE_BASE + 128 * WSTR)
#define OFF_BH (TILE_BASE + 256 * WSTR)
#define OFF_BL (TILE_BASE + 384 * WSTR)
#define K1_SMEM_BYTES ((TILE_BASE + 512 * WSTR) * 4)   // 204800 B

__device__ __forceinline__ void mma_bf16(float& c0, float& c1, float& c2, float& c3,
                                         uint32_t a0, uint32_t a1, uint32_t a2,
                                         uint32_t a3, uint32_t b0, uint32_t b1) {
    asm volatile(
        "mma.sync.aligned.m16n8k16.row.col.f32.bf16.bf16.f32 "
        "{%0,%1,%2,%3}, {%4,%5,%6,%7}, {%8,%9}, {%0,%1,%2,%3};"
        : "+f"(c0), "+f"(c1), "+f"(c2), "+f"(c3)
        : "r"(a0), "r"(a1), "r"(a2), "r"(a3), "r"(b0), "r"(b1));
}

__device__ __forceinline__ void k1_issue_slice(const float* __restrict__ H,
                                               const float* __restrict__ X,
                                               int n0s, int t0, int buf,
                                               uint32_t smb, int tid) {
    const uint32_t stH = smb + (uint32_t)((buf * 2 + 0) * STG_MAT) * 4u;
    const uint32_t stX = smb + (uint32_t)((buf * 2 + 1) * STG_MAT) * 4u;
#pragma unroll
    for (int i = 0; i < 4; i++) {
        int ch = tid + i * 512;          // 0..2047
        int r = ch >> 5;                 // staging row 0..63
        int j = ch & 31;                 // 16B chunk within row
        int js = j ^ ((r >> 1) & 7);     // swizzle (low 3 bits)
        uint32_t doff = (uint32_t)(r * 512 + js * 16);
        int n = n0s + r;
        if (n < N_NODES) {
            const float* gH = H + (size_t)n * T_SEQ + t0 + j * 4;
            const float* gX = X + (size_t)n * IN_CH + j * 4;
            asm volatile("cp.async.ca.shared.global [%0], [%1], 16;"
                         :: "r"(stH + doff), "l"(gH));
            asm volatile("cp.async.ca.shared.global [%0], [%1], 16;"
                         :: "r"(stX + doff), "l"(gX));
        } else {
            asm volatile("st.shared.v4.u32 [%0], {%1,%1,%1,%1};"
                         :: "r"(stH + doff), "r"(0u) : "memory");
            asm volatile("st.shared.v4.u32 [%0], {%1,%1,%1,%1};"
                         :: "r"(stX + doff), "r"(0u) : "memory");
        }
    }
}

__global__ void __launch_bounds__(512, 1) k1h_kernel(const float* __restrict__ H,
                                                     const float* __restrict__ X) {
    extern __shared__ uint32_t smw[];
    float* stf = (float*)smw;
    uint32_t smb;
    asm("{ .reg .u64 t; cvta.to.shared.u64 t, %1; cvt.u32.u64 %0, t; }"
        : "=r"(smb) : "l"((const void*)smw));

    const int tid = threadIdx.x;
    const int t0 = blockIdx.x * 128;
    const int n0 = blockIdx.y * K1_CHUNK;

    const int kp = tid & 31;
    const int mg = tid >> 5;
    const int kx = kp & 7;

    const int wid = tid >> 5, lane = tid & 31;
    const int wm = wid >> 2, wn = wid & 3;
    const int lr = lane >> 2, lc = lane & 3;

    float c[2][4][4];
#pragma unroll
    for (int mt = 0; mt < 2; mt++)
#pragma unroll
        for (int nt = 0; nt < 4; nt++)
#pragma unroll
            for (int r = 0; r < 4; r++) c[mt][nt][r] = 0.f;

    k1_issue_slice(H, X, n0, t0, 0, smb, tid);
    asm volatile("cp.async.commit_group;" ::: "memory");

    for (int s = 0; s < NSLICES; s++) {
        const int buf = s & 1;

        if (s + 1 < NSLICES) {
            k1_issue_slice(H, X, n0 + (s + 1) * 64, t0, buf ^ 1, smb, tid);
            asm volatile("cp.async.commit_group;" ::: "memory");
            asm volatile("cp.async.wait_group 1;" ::: "memory");
        } else {
            asm volatile("cp.async.wait_group 0;" ::: "memory");
        }
        __syncthreads();   // staging[buf] visible to all

#pragma unroll
        for (int tsel = 0; tsel < 2; tsel++) {
            const int so = (buf * 2 + tsel) * STG_MAT;
            const int offh = tsel ? OFF_BH : OFF_AH;
            const int offl = tsel ? OFF_BL : OFF_AL;
            const float* r0p = stf + so + (2 * kp) * STG_ROW;
            const float* r1p = stf + so + (2 * kp + 1) * STG_ROW;
            float4 v00 = *(const float4*)(r0p + (((2 * mg)     ^ kx) << 2));
            float4 v01 = *(const float4*)(r0p + (((2 * mg + 1) ^ kx) << 2));
            float4 v10 = *(const float4*)(r1p + (((2 * mg)     ^ kx) << 2));
            float4 v11 = *(const float4*)(r1p + (((2 * mg + 1) ^ kx) << 2));
            const float* e0 = &v00.x;
            const float* f0 = &v01.x;
            const float* e1 = &v10.x;
            const float* f1 = &v11.x;
#pragma unroll
            for (int j = 0; j < 8; j++) {
                float v0 = (j < 4) ? e0[j] : f0[j - 4];
                float v1 = (j < 4) ? e1[j] : f1[j - 4];
                __nv_bfloat162 hi2 = __floats2bfloat162_rn(v0, v1);
                float l0 = v0 - __bfloat162float(hi2.x);
                float l1 = v1 - __bfloat162float(hi2.y);
                __nv_bfloat162 lo2 = __floats2bfloat162_rn(l0, l1);
                int m = mg * 8 + j;
                smw[offh + m * WSTR + kp] = *(uint32_t*)&hi2;
                smw[offl + m * WSTR + kp] = *(uint32_t*)&lo2;
            }
        }

        __syncthreads();   // tiles visible

#pragma unroll
        for (int ks = 0; ks < 4; ks++) {
            const int ksw = ks * 8;
            uint32_t ah[2][4], al[2][4], bh[4][2], bl[4][2];
#pragma unroll
            for (int mt = 0; mt < 2; mt++) {
                int row = wm * 32 + mt * 16 + lr;
                const uint32_t* pa = smw + row * WSTR + ksw + lc;
                ah[mt][0] = pa[OFF_AH];
                ah[mt][1] = pa[OFF_AH + 8 * WSTR];
                ah[mt][2] = pa[OFF_AH + 4];
                ah[mt][3] = pa[OFF_AH + 8 * WSTR + 4];
                al[mt][0] = pa[OFF_AL];
                al[mt][1] = pa[OFF_AL + 8 * WSTR];
                al[mt][2] = pa[OFF_AL + 4];
                al[mt][3] = pa[OFF_AL + 8 * WSTR + 4];
            }
#pragma unroll
            for (int nt = 0; nt < 4; nt++) {
                int nrow = wn * 32 + nt * 8 + lr;
                const uint32_t* pb = smw + nrow * WSTR + ksw + lc;
                bh[nt][0] = pb[OFF_BH];
                bh[nt][1] = pb[OFF_BH + 4];
                bl[nt][0] = pb[OFF_BL];
                bl[nt][1] = pb[OFF_BL + 4];
            }
#pragma unroll
            for (int mt = 0; mt < 2; mt++)
#pragma unroll
                for (int nt = 0; nt < 4; nt++) {
                    float* cc = c[mt][nt];
                    mma_bf16(cc[0], cc[1], cc[2], cc[3],
                             ah[mt][0], ah[mt][1], ah[mt][2], ah[mt][3],
                             bh[nt][0], bh[nt][1]);
                    mma_bf16(cc[0], cc[1], cc[2], cc[3],
                             ah[mt][0], ah[mt][1], ah[mt][2], ah[mt][3],
                             bl[nt][0], bl[nt][1]);
                    mma_bf16(cc[0], cc[1], cc[2], cc[3],
                             al[mt][0], al[mt][1], al[mt][2], al[mt][3],
                             bh[nt][0], bh[nt][1]);
                }
        }

        __syncthreads();   // MMA reads done before next slice's stores
    }

    float* pp = g_part + (size_t)blockIdx.y * (T_SEQ * IN_CH);
#pragma unroll
    for (int mt = 0; mt < 2; mt++) {
#pragma unroll
        for (int nt = 0; nt < 4; nt++) {
            int row0 = wm * 32 + mt * 16 + lr;
            int col = wn * 32 + nt * 8 + lc * 2;
            *(float2*)(pp + (size_t)(t0 + row0) * IN_CH + col) =
                make_float2(c[mt][nt][0], c[mt][nt][1]);
            *(float2*)(pp + (size_t)(t0 + row0 + 8) * IN_CH + col) =
                make_float2(c[mt][nt][2], c[mt][nt][3]);
        }
    }
}

// K1b: ve = sum over 37 chunk partials (512 blocks -> high MLP; round-12-proven)
__global__ void __launch_bounds__(256) k1_reduce_kernel() {
    int idx = blockIdx.x * blockDim.x + threadIdx.x;   // 0..131071
    float s = 0.f;
#pragma unroll
    for (int c = 0; c < K1_NCHUNK; c++) s += g_part[c * (T_SEQ * IN_CH) + idx];
    g_ve[idx] = s;
}

// ============================================================================
// K2: gx[t][r] = b_ih[r] + sum_k ve[t][k]*w_ih[r][k]  (round-12-proven)
// ============================================================================
__global__ void __launch_bounds__(256) gx_kernel(const float* __restrict__ w_ih,
                                                 const float* __restrict__ b_ih) {
    const int t = blockIdx.x;
    const int w = threadIdx.x >> 5, l = threadIdx.x & 31;
    float4 vv = *(const float4*)(g_ve + t * IN_CH + l * 4);
    for (int rr = 0; rr < 96; rr++) {
        int r = w * 96 + rr;
        float4 wv = *(const float4*)(w_ih + (size_t)r * IN_CH + l * 4);
        float p = vv.x * wv.x + vv.y * wv.y + vv.z * wv.z + vv.w * wv.w;
#pragma unroll
        for (int o = 16; o; o >>= 1) p += __shfl_xor_sync(0xffffffffu, p, o);
        if (l == 0) g_gx[t * G3 + r] = p + b_ih[r];
    }
}

// ============================================================================
// K3: sequential GRU, 16-CTA cluster x 128 threads — round-12-proven (603us,
// fabric-latency floor). hnew staged to SMEM (16 floats), one __syncthreads
// (read-certificate + stage-complete), then 64 vector sends: thread tid<64
// sends 16B (st.async.v4) chunk tid&3 to peer tid>>2.
// ============================================================================
#define GRU_NCTA 16
__device__ __forceinline__ void cluster_sync_() {
    asm volatile("barrier.cluster.arrive.aligned;" ::: "memory");
    asm volatile("barrier.cluster.wait.aligned;" ::: "memory");
}
__device__ __forceinline__ void st_async_v4(uint32_t laddr, uint32_t lbar,
                                            uint32_t peer, float4 v) {
    uint32_t ra, rb;
    asm volatile("mapa.shared::cluster.u32 %0, %1, %2;"
                 : "=r"(ra) : "r"(laddr), "r"(peer));
    asm volatile("mapa.shared::cluster.u32 %0, %1, %2;"
                 : "=r"(rb) : "r"(lbar), "r"(peer));
    asm volatile(
        "st.async.shared::cluster.mbarrier::complete_tx::bytes.v4.b32 "
        "[%0], {%1,%2,%3,%4}, [%5];"
        :: "r"(ra), "r"(__float_as_uint(v.x)), "r"(__float_as_uint(v.y)),
           "r"(__float_as_uint(v.z)), "r"(__float_as_uint(v.w)), "r"(rb)
        : "memory");
}
__device__ __forceinline__ void arm_expect_tx(uint32_t bar, uint32_t bytes) {
    asm volatile("mbarrier.arrive.expect_tx.shared.b64 _, [%0], %1;"
                 :: "r"(bar), "r"(bytes) : "memory");
}
__device__ __forceinline__ void wait_parity_cl(uint32_t bar, uint32_t par) {
    uint32_t done;
    do {
        asm volatile(
            "{\n\t.reg .pred p;\n\t"
            "mbarrier.try_wait.parity.acquire.cluster.shared::cta.b64 p, [%1], %2, 0x989680;\n\t"
            "selp.b32 %0, 1, 0, p;\n\t}"
            : "=r"(done) : "r"(bar), "r"(par) : "memory");
    } while (!done);
}
__device__ __forceinline__ float tanh_ap(float x) {
    float y;
    asm("tanh.approx.f32 %0, %1;" : "=f"(y) : "f"(x));
    return y;
}
__device__ __forceinline__ float sigmoid_ap(float x) {
    return fmaf(0.5f, tanh_ap(0.5f * x), 0.5f);
}

__global__ void __launch_bounds__(128, 1)
gru_kernel(const float* __restrict__ w_hh, const float* __restrict__ b_hh) {
    __shared__ __align__(16) float sh_h[2][256];            // double-buffered h
    __shared__ __align__(16) float sh_stage[16];            // this CTA's hnew
    __shared__ __align__(8) unsigned long long sh_bar[2];   // full barrier per buf

    const int tid = threadIdx.x;
    const int rank = blockIdx.x;       // 0..15
    const int j = tid >> 3;            // slot 0..15
    const int o = tid & 7;             // k-octant 0..7
    const int slot = rank * 16 + j;    // global h index owned by this group

    unsigned long long wr[16], wz[16], wn[16];
#pragma unroll
    for (int i = 0; i < 16; i++) {
        int k = o * 32 + ((i + 2 * o) & 15) * 2;
        wr[i] = *(const unsigned long long*)(w_hh + (size_t)(slot)*256 + k);
        wz[i] = *(const unsigned long long*)(w_hh + (size_t)(256 + slot) * 256 + k);
        wn[i] = *(const unsigned long long*)(w_hh + (size_t)(512 + slot) * 256 + k);
    }
    const float bhr = b_hh[slot];
    const float bhz = b_hh[256 + slot];
    const float bhn = b_hh[512 + slot];

    sh_h[0][tid] = 0.f;   sh_h[0][tid + 128] = 0.f;
    sh_h[1][tid] = 0.f;   sh_h[1][tid + 128] = 0.f;
    uint32_t bbase = (uint32_t)__cvta_generic_to_shared(&sh_bar[0]);
    if (tid == 0) {
        asm volatile("mbarrier.init.shared.b64 [%0], %1;" :: "r"(bbase),     "r"(1) : "memory");
        asm volatile("mbarrier.init.shared.b64 [%0], %1;" :: "r"(bbase + 8), "r"(1) : "memory");
        arm_expect_tx(bbase, 1024u);       // buffer-0 stores (written at step 1)
        arm_expect_tx(bbase + 8, 1024u);   // buffer-1 stores (written at step 0)
    }
    __syncthreads();
    cluster_sync_();   // barriers + h0 visible cluster-wide

    for (int t = 0; t < T_SEQ; t++) {
        const int cur = t & 1, nxt = cur ^ 1;

        // gx loads (h-independent) issued before the wait to hide latency
        const float gxr = g_gx[t * G3 + slot];
        const float gxz = g_gx[t * G3 + 256 + slot];
        const float gxn = g_gx[t * G3 + 512 + slot];

        if (t > 0) {
            wait_parity_cl(bbase + 8u * (uint32_t)cur, ((t - 1) >> 1) & 1);
            if (tid == 0) arm_expect_tx(bbase + 8u * (uint32_t)cur, 1024u);
        }

        const float hprev = sh_h[cur][slot];

        unsigned long long ar = 0ull, az = 0ull, an = 0ull;
        {
            const float* hb = &sh_h[cur][0];
#pragma unroll
            for (int i = 0; i < 16; i++) {
                int k = o * 32 + ((i + 2 * o) & 15) * 2;
                unsigned long long hv = *(const unsigned long long*)(hb + k);
                asm("fma.rn.f32x2 %0, %1, %2, %0;" : "+l"(ar) : "l"(wr[i]), "l"(hv));
                asm("fma.rn.f32x2 %0, %1, %2, %0;" : "+l"(az) : "l"(wz[i]), "l"(hv));
                asm("fma.rn.f32x2 %0, %1, %2, %0;" : "+l"(an) : "l"(wn[i]), "l"(hv));
            }
        }
        float pr, pz, pn;
        {
            float lo, hi;
            asm("mov.b64 {%0, %1}, %2;" : "=f"(lo), "=f"(hi) : "l"(ar)); pr = lo + hi;
            asm("mov.b64 {%0, %1}, %2;" : "=f"(lo), "=f"(hi) : "l"(az)); pz = lo + hi;
            asm("mov.b64 {%0, %1}, %2;" : "=f"(lo), "=f"(hi) : "l"(an)); pn = lo + hi;
        }
#pragma unroll
        for (int d = 1; d < 8; d <<= 1) {
            pr += __shfl_xor_sync(0xffffffffu, pr, d);
            pz += __shfl_xor_sync(0xffffffffu, pz, d);
            pn += __shfl_xor_sync(0xffffffffu, pn, d);
        }

        const float r = sigmoid_ap(gxr + pr + bhr);
        const float z = sigmoid_ap(gxz + pz + bhz);
        const float n = tanh_ap(gxn + r * (pn + bhn));
        const float hnew = n + z * (hprev - n);

        if (o == 0) {
            sh_stage[j] = hnew;
            g_hs[t * HID + slot] = hnew;
        }

        if (t < T_SEQ - 1) {
            // certifies: all reads of sh_h[cur] retired AND sh_stage complete
            __syncthreads();
            if (tid < 64) {
                const int peer = tid >> 2;       // 0..15 (incl. self)
                const int chunk = tid & 3;       // 0..3 (4 slots each)
                float4 v = *(const float4*)&sh_stage[chunk * 4];
                uint32_t laddr = (uint32_t)__cvta_generic_to_shared(
                    &sh_h[nxt][rank * 16 + chunk * 4]);
                st_async_v4(laddr, bbase + 8u * (uint32_t)nxt, (uint32_t)peer, v);
            }
        }
    }
    cluster_sync_();   // drain in-flight traffic before exit
}

// ============================================================================
// K4: logits = hs @ w_attn; alpha = softmax(logits); out = alpha @ hs
// (round-12-proven, 28us)
// ============================================================================
__global__ void __launch_bounds__(1024) attn_kernel(const float* __restrict__ w_attn,
                                                    float* __restrict__ out) {
    __shared__ float s_alpha[1024];
    __shared__ float s_red[1024];
    __shared__ float s_wa[256];
    const int tid = threadIdx.x;
    if (tid < 256) s_wa[tid] = w_attn[tid];
    __syncthreads();

    const int w = tid >> 5, l = tid & 31;
    for (int tt = 0; tt < 32; tt++) {
        int t = w * 32 + tt;
        const float* hr = g_hs + t * HID;
        float p = 0.f;
#pragma unroll
        for (int j = 0; j < 8; j++) p = fmaf(hr[l + 32 * j], s_wa[l + 32 * j], p);
#pragma unroll
        for (int o = 16; o; o >>= 1) p += __shfl_xor_sync(0xffffffffu, p, o);
        if (l == 0) s_alpha[t] = p;
    }
    __syncthreads();

    float v = s_alpha[tid];
    s_red[tid] = v;
    __syncthreads();
    for (int s = 512; s; s >>= 1) {
        if (tid < s) s_red[tid] = fmaxf(s_red[tid], s_red[tid + s]);
        __syncthreads();
    }
    float m = s_red[0];
    __syncthreads();
    float e = __expf(v - m);
    s_red[tid] = e;
    __syncthreads();
    for (int s = 512; s; s >>= 1) {
        if (tid < s) s_red[tid] = s_red[tid] + s_red[tid + s];
        __syncthreads();
    }
    float inv = 1.f / s_red[0];
    __syncthreads();
    s_alpha[tid] = e * inv;
    __syncthreads();

    const int j = tid & 255, seg = tid >> 8;
    float p = 0.f;
    const float* hp = g_hs + (size_t)seg * 256 * HID + j;
    const float* ap = s_alpha + seg * 256;
    for (int t = 0; t < 256; t++) p = fmaf(ap[t], hp[t * HID], p);
    s_red[tid] = p;
    __syncthreads();
    if (tid < 256)
        out[j] = (s_red[j] + s_red[256 + j]) + (s_red[512 + j] + s_red[768 + j]);
}

// ============================================================================
extern "C" void kernel_launch(void* const* d_in, const int* in_sizes, int n_in,
                              void* d_out, int out_size) {
    const float* X = nullptr;
    const float* H = nullptr;
    const float* w_ih = nullptr;
    const float* w_hh = nullptr;
    const float* b_ih = nullptr;
    const float* b_hh = nullptr;
    const float* w_attn = nullptr;
    for (int i = 0; i < n_in; i++) {
        int s = in_sizes[i];
        const float* p = (const float*)d_in[i];
        if (s == N_NODES * IN_CH)      X = p;
        else if (s == N_NODES * T_SEQ) H = p;
        else if (s == G3 * IN_CH)      w_ih = p;
        else if (s == G3 * HID)        w_hh = p;
        else if (s == G3) { if (!b_ih) b_ih = p; else b_hh = p; }
        else if (s == HID)             w_attn = p;
    }
    float* out = (float*)d_out;

    cudaFuncSetAttribute(k1h_kernel, cudaFuncAttributeMaxDynamicSharedMemorySize,
                         K1_SMEM_BYTES);

    k1h_kernel<<<dim3(8, K1_NCHUNK), 512, K1_SMEM_BYTES>>>(H, X);
    k1_reduce_kernel<<<(T_SEQ * IN_CH) / 256, 256>>>();
    gx_kernel<<<T_SEQ, 256>>>(w_ih, b_ih);

    // GRU: 16-CTA cluster (non-portable size), runtime cluster attribute
    cudaFuncSetAttribute(gru_kernel,
                         cudaFuncAttributeNonPortableClusterSizeAllowed, 1);
    {
        cudaLaunchConfig_t cfg = {};
        cfg.gridDim = dim3(GRU_NCTA, 1, 1);
        cfg.blockDim = dim3(128, 1, 1);
        cfg.dynamicSmemBytes = 0;
        cudaLaunchAttribute attrs[1];
        attrs[0].id = cudaLaunchAttributeClusterDimension;
        attrs[0].val.clusterDim = {GRU_NCTA, 1, 1};
        cfg.attrs = attrs;
        cfg.numAttrs = 1;
        cudaLaunchKernelEx(&cfg, gru_kernel, w_hh, b_hh);
    }

    attn_kernel<<<1, 1024>>>(w_attn, out);
}